// round 5
// baseline (speedup 1.0000x reference)
#include <cuda_runtime.h>
#include <math.h>

#define S_ 8192
#define D_ 64
#define N_ 2048
#define O_ 8
#define GATHER_BLOCKS 256                 // 256 x 256 thr = 65536 = S_*O_
#define LSE_BLOCKS (2 * N_ + O_ + N_ / 8) // 4360 arrival count

// ---- scratch (allocation-free rule: __device__ globals; BSS = 0) ----
__device__ float d_lse0[N_];
__device__ float d_lse1[N_];
__device__ float d_lse2[N_];
__device__ float d_lse_out[O_];
// One ready-flag PER GATHER BLOCK, each on its own 128B line. R3/R4 regressed
// because all pollers hammered ONE address: strong ops to a single address
// serialize at one LTS slice (~tens of M ops/s) and the backed-up queue
// throttled the entire L2 (DRAM stuck at ~37%). Distinct lines spread the
// (already low-rate) polls across all LTS slices.
__device__ unsigned d_flags[GATHER_BLOCKS * 32];
__device__ __align__(128) unsigned d_lse_done;   // LSE arrivals
__device__ __align__(128) unsigned d_g_done;     // gather arrivals (for reset)

__device__ __forceinline__ unsigned ld_acquire_u32(const unsigned* p) {
    unsigned v;
    asm volatile("ld.acquire.gpu.u32 %0, [%1];" : "=r"(v) : "l"(p));
    return v;
}
__device__ __forceinline__ void st_release_u32(unsigned* p, unsigned v) {
    asm volatile("st.release.gpu.u32 [%0], %1;" :: "l"(p), "r"(v) : "memory");
}

// ---------------------------------------------------------------------------
// Single merged kernel.
//   blocks [0, GATHER_BLOCKS)  : path walk -> wait on PRIVATE flag -> normalize
//   remaining blocks           : row-wise logsumexp; last arrival broadcasts
//                                the ready signal to all 256 private flags.
// ---------------------------------------------------------------------------
__global__ void __launch_bounds__(256) occamnet_kernel(const float* __restrict__ x,
                                                       const float* __restrict__ w0,
                                                       const float* __restrict__ w1,
                                                       const float* __restrict__ w2,
                                                       const float* __restrict__ w_out,
                                                       const int* __restrict__ c0,
                                                       const int* __restrict__ c1,
                                                       const int* __restrict__ c2,
                                                       const int* __restrict__ keys_out,
                                                       float* __restrict__ out)
{
    __shared__ float smax[8];
    __shared__ float ssum[8];
    __shared__ unsigned s_last;

    const int b = blockIdx.x;
    const int t = threadIdx.x;
    const int lane = t & 31;
    const int warp = t >> 5;

    if (b < GATHER_BLOCKS) {
        // ================= path-walk gather =================
        const int tid = b * 256 + t;
        const int s = tid >> 3;          // / O_
        const int o = tid & 7;           // % O_

        const int r2 = keys_out[tid];
        float logp = w_out[o * N_ + r2];

        const int r1 = c2[(size_t)s * N_ + r2];
        logp += w2[(size_t)r2 * N_ + r1];

        const int r0 = c1[(size_t)s * N_ + r1];
        logp += w1[(size_t)r1 * N_ + r0];

        const int cin = c0[(size_t)s * N_ + r0];
        logp += w0[r0 * D_ + cin];

        const float y = sinf(sinf(sinf(x[s * D_ + cin])));
        out[tid] = y;                                        // [0, S, O] slice

        // Wait on this block's PRIVATE flag line (no cross-block contention).
        unsigned* myflag = &d_flags[b * 32];
        if (t == 0) {
            while (ld_acquire_u32(myflag) == 0u)
                __nanosleep(256);
        }
        __syncthreads();

        // Table reads bypass L1 (L2-only): written this launch by other SMs.
        logp -= __ldcg(&d_lse_out[o]) + __ldcg(&d_lse2[r2])
              + __ldcg(&d_lse1[r1])   + __ldcg(&d_lse0[r0]);
        out[S_ * O_ + tid] = expf(logp);                     // [1, S, O] slice

        if (t == 0) {
            *myflag = 0u;                // self-reset for next graph replay
            unsigned old = atomicAdd(&d_g_done, 1u);
            if (old == GATHER_BLOCKS - 1) {                  // last gather block
                atomicExch(&d_lse_done, 0u);                 // (all LSE arrivals
                atomicExch(&d_g_done, 0u);                   //  long finished)
            }
        }
        return;
    }

    const int b2 = b - GATHER_BLOCKS;
    if (b2 < 2 * N_ + O_) {
        // ================= wide rows: 2048 elements =================
        const float* row;
        float* dst;
        if (b2 < N_)          { row = w1    + (size_t)b2 * N_;           dst = &d_lse1[b2]; }
        else if (b2 < 2 * N_) { row = w2    + (size_t)(b2 - N_) * N_;    dst = &d_lse2[b2 - N_]; }
        else                  { row = w_out + (size_t)(b2 - 2*N_) * N_;  dst = &d_lse_out[b2 - 2*N_]; }

        const float4* row4 = (const float4*)row;
        float4 a = row4[t];
        float4 c = row4[t + 256];
        float v[8] = {a.x, a.y, a.z, a.w, c.x, c.y, c.z, c.w};

        float m = v[0];
        #pragma unroll
        for (int i = 1; i < 8; i++) m = fmaxf(m, v[i]);
        #pragma unroll
        for (int off = 16; off; off >>= 1) m = fmaxf(m, __shfl_xor_sync(0xffffffffu, m, off));
        if (lane == 0) smax[warp] = m;
        __syncthreads();
        float bm = smax[0];
        #pragma unroll
        for (int i = 1; i < 8; i++) bm = fmaxf(bm, smax[i]);

        float ss = 0.0f;
        #pragma unroll
        for (int i = 0; i < 8; i++) ss += expf(v[i] - bm);
        #pragma unroll
        for (int off = 16; off; off >>= 1) ss += __shfl_xor_sync(0xffffffffu, ss, off);
        if (lane == 0) ssum[warp] = ss;
        __syncthreads();
        if (t == 0) {
            float tot = 0.0f;
            #pragma unroll
            for (int i = 0; i < 8; i++) tot += ssum[i];
            *dst = bm + logf(tot);
            __threadfence();                               // release the row
            unsigned old = atomicAdd(&d_lse_done, 1u);     // arrive
            s_last = (old == (unsigned)LSE_BLOCKS - 1) ? 1u : 0u;
        }
        __syncthreads();
        if (s_last)                                        // last LSE block:
            st_release_u32(&d_flags[t * 32], 1u);          // 256-wide broadcast
    } else {
        // ================= w0: 64-wide rows, one warp per row =================
        const int r = (b2 - (2 * N_ + O_)) * 8 + warp;
        const float* row = w0 + (size_t)r * D_;
        float v0 = row[lane];
        float v1 = row[lane + 32];
        float m = fmaxf(v0, v1);
        #pragma unroll
        for (int off = 16; off; off >>= 1) m = fmaxf(m, __shfl_xor_sync(0xffffffffu, m, off));
        float ss = expf(v0 - m) + expf(v1 - m);
        #pragma unroll
        for (int off = 16; off; off >>= 1) ss += __shfl_xor_sync(0xffffffffu, ss, off);
        if (lane == 0) d_lse0[r] = m + logf(ss);
        __syncthreads();                                   // all 8 rows written
        if (t == 0) {
            __threadfence();                               // release
            unsigned old = atomicAdd(&d_lse_done, 1u);     // arrive
            s_last = (old == (unsigned)LSE_BLOCKS - 1) ? 1u : 0u;
        }
        __syncthreads();
        if (s_last)
            st_release_u32(&d_flags[t * 32], 1u);
    }
}

extern "C" void kernel_launch(void* const* d_in, const int* in_sizes, int n_in,
                              void* d_out, int out_size)
{
    const float* x     = (const float*)d_in[0];
    const float* w0    = (const float*)d_in[1];
    const float* w1    = (const float*)d_in[2];
    const float* w2    = (const float*)d_in[3];
    const float* w_out = (const float*)d_in[4];
    const int*   c0    = (const int*)d_in[5];
    const int*   c1    = (const int*)d_in[6];
    const int*   c2    = (const int*)d_in[7];
    const int*   keys  = (const int*)d_in[8];
    float*       out   = (float*)d_out;

    const int blocks = GATHER_BLOCKS + LSE_BLOCKS;
    occamnet_kernel<<<blocks, 256>>>(x, w0, w1, w2, w_out,
                                     c0, c1, c2, keys, out);
}

// round 6
// speedup vs baseline: 1.4372x; 1.4372x over previous
#include <cuda_runtime.h>
#include <math.h>

#define S_ 8192
#define D_ 64
#define N_ 2048
#define O_ 8
#define GATHER_BLOCKS 256                 // 256 x 256 thr = 65536 = S_*O_
#define LSE_BLOCKS (2 * N_ + O_ + N_ / 8) // 4360

// ---- scratch (allocation-free rule: __device__ globals) ----
__device__ float d_lse0[N_];
__device__ float d_lse1[N_];
__device__ float d_lse2[N_];
__device__ float d_lse_out[O_];
__device__ uint4 d_walk[S_ * O_];   // {bits(logp_raw), r2, r1, r0}

// ---------------------------------------------------------------------------
// Kernel A (R2 structure, measured 9.2us): blocks [0, GATHER_BLOCKS) walk the
// sampled paths (un-normalized log-prob) while the remaining blocks compute
// the row-wise logsumexp tables. Gather blocks go first so their latency
// slack hides the LSE streaming.
// ---------------------------------------------------------------------------
__global__ void __launch_bounds__(256) lse_gather_kernel(const float* __restrict__ x,
                                                         const float* __restrict__ w0,
                                                         const float* __restrict__ w1,
                                                         const float* __restrict__ w2,
                                                         const float* __restrict__ w_out,
                                                         const int* __restrict__ c0,
                                                         const int* __restrict__ c1,
                                                         const int* __restrict__ c2,
                                                         const int* __restrict__ keys_out,
                                                         float* __restrict__ out)
{
    __shared__ float smax[8];
    __shared__ float ssum[8];

    const int b = blockIdx.x;
    const int t = threadIdx.x;
    const int lane = t & 31;
    const int warp = t >> 5;

    if (b < GATHER_BLOCKS) {
        // ================= path-walk gather (un-normalized) =================
        const int tid = b * 256 + t;
        const int s = tid >> 3;          // / O_
        const int o = tid & 7;           // % O_

        const int r2 = keys_out[tid];
        float logp = w_out[o * N_ + r2];

        const int r1 = c2[(size_t)s * N_ + r2];
        logp += w2[(size_t)r2 * N_ + r1];

        const int r0 = c1[(size_t)s * N_ + r1];
        logp += w1[(size_t)r1 * N_ + r0];

        const int cin = c0[(size_t)s * N_ + r0];
        logp += w0[r0 * D_ + cin];

        const float y = __sinf(__sinf(__sinf(x[s * D_ + cin])));
        out[tid] = y;                                        // [0, S, O] slice

        d_walk[tid] = make_uint4(__float_as_uint(logp),
                                 (unsigned)r2, (unsigned)r1, (unsigned)r0);
        return;
    }

    const int b2 = b - GATHER_BLOCKS;
    if (b2 < 2 * N_ + O_) {
        // ================= wide rows: 2048 elements =================
        const float* row;
        float* dst;
        if (b2 < N_)          { row = w1    + (size_t)b2 * N_;           dst = &d_lse1[b2]; }
        else if (b2 < 2 * N_) { row = w2    + (size_t)(b2 - N_) * N_;    dst = &d_lse2[b2 - N_]; }
        else                  { row = w_out + (size_t)(b2 - 2*N_) * N_;  dst = &d_lse_out[b2 - 2*N_]; }

        const float4* row4 = (const float4*)row;
        float4 a = row4[t];
        float4 c = row4[t + 256];
        float v[8] = {a.x, a.y, a.z, a.w, c.x, c.y, c.z, c.w};

        float m = v[0];
        #pragma unroll
        for (int i = 1; i < 8; i++) m = fmaxf(m, v[i]);
        #pragma unroll
        for (int off = 16; off; off >>= 1) m = fmaxf(m, __shfl_xor_sync(0xffffffffu, m, off));
        if (lane == 0) smax[warp] = m;
        __syncthreads();
        float bm = smax[0];
        #pragma unroll
        for (int i = 1; i < 8; i++) bm = fmaxf(bm, smax[i]);

        float ss = 0.0f;
        #pragma unroll
        for (int i = 0; i < 8; i++) ss += __expf(v[i] - bm);
        #pragma unroll
        for (int off = 16; off; off >>= 1) ss += __shfl_xor_sync(0xffffffffu, ss, off);
        if (lane == 0) ssum[warp] = ss;
        __syncthreads();
        if (t == 0) {
            float tot = 0.0f;
            #pragma unroll
            for (int i = 0; i < 8; i++) tot += ssum[i];
            *dst = bm + __logf(tot);
        }
    } else {
        // ================= w0: 64-wide rows, one warp per row =================
        const int r = (b2 - (2 * N_ + O_)) * 8 + warp;
        const float* row = w0 + (size_t)r * D_;
        float v0 = row[lane];
        float v1 = row[lane + 32];
        float m = fmaxf(v0, v1);
        #pragma unroll
        for (int off = 16; off; off >>= 1) m = fmaxf(m, __shfl_xor_sync(0xffffffffu, m, off));
        float ss = __expf(v0 - m) + __expf(v1 - m);
        #pragma unroll
        for (int off = 16; off; off >>= 1) ss += __shfl_xor_sync(0xffffffffu, ss, off);
        if (lane == 0) d_lse0[r] = m + __logf(ss);
    }
}

// ---------------------------------------------------------------------------
// Kernel B: finalize with the LSE tables STAGED IN SHARED MEMORY.
// R2's finalize spent ~5.6us because each thread issued 4 fully-divergent
// global loads (32 L1tex wavefronts per warp-load). With the 24.2 KB of
// tables in smem, those become cheap LDS ops; the only global traffic is one
// coalesced uint4 scratch read and one coalesced float store per thread.
// ---------------------------------------------------------------------------
__global__ void __launch_bounds__(256) finalize_kernel(float* __restrict__ out)
{
    __shared__ float s_lse0[N_];
    __shared__ float s_lse1[N_];
    __shared__ float s_lse2[N_];
    __shared__ float s_lse_out[O_];

    const int t = threadIdx.x;

    // cooperative table load: coalesced float4 from L2-resident globals
    const float4* g0 = (const float4*)d_lse0;
    const float4* g1 = (const float4*)d_lse1;
    const float4* g2 = (const float4*)d_lse2;
    #pragma unroll
    for (int i = 0; i < N_ / 4 / 256; i++) {      // 2 iters
        ((float4*)s_lse0)[t + i * 256] = g0[t + i * 256];
        ((float4*)s_lse1)[t + i * 256] = g1[t + i * 256];
        ((float4*)s_lse2)[t + i * 256] = g2[t + i * 256];
    }
    if (t < O_) s_lse_out[t] = d_lse_out[t];
    __syncthreads();

    const int tid = blockIdx.x * blockDim.x + t;
    const int o = tid & 7;

    const uint4 wlk = d_walk[tid];
    const float logp = __uint_as_float(wlk.x)
                     - s_lse_out[o] - s_lse2[wlk.y] - s_lse1[wlk.z] - s_lse0[wlk.w];
    out[S_ * O_ + tid] = __expf(logp);            // [1, S, O] slice
}

extern "C" void kernel_launch(void* const* d_in, const int* in_sizes, int n_in,
                              void* d_out, int out_size)
{
    const float* x     = (const float*)d_in[0];
    const float* w0    = (const float*)d_in[1];
    const float* w1    = (const float*)d_in[2];
    const float* w2    = (const float*)d_in[3];
    const float* w_out = (const float*)d_in[4];
    const int*   c0    = (const int*)d_in[5];
    const int*   c1    = (const int*)d_in[6];
    const int*   c2    = (const int*)d_in[7];
    const int*   keys  = (const int*)d_in[8];
    float*       out   = (float*)d_out;

    const int blocksA = GATHER_BLOCKS + LSE_BLOCKS;
    lse_gather_kernel<<<blocksA, 256>>>(x, w0, w1, w2, w_out,
                                        c0, c1, c2, keys, out);

    finalize_kernel<<<GATHER_BLOCKS, 256>>>(out);
}